// round 5
// baseline (speedup 1.0000x reference)
#include <cuda_runtime.h>
#include <cuda_bf16.h>
#include <cstdint>

#define B_ 8
#define N_ 1024
#define E_ 1024
#define H_ 16
#define D_ 64

// ---------------------------------------------------------------------------
// Static scratch (allocation-free)
// ---------------------------------------------------------------------------
#define QKV_ELEMS ((size_t)B_ * H_ * N_ * D_)
__device__ __align__(16) __nv_bfloat16 g_qh[QKV_ELEMS];
__device__ __align__(16) __nv_bfloat16 g_ql[QKV_ELEMS];
__device__ __align__(16) __nv_bfloat16 g_kh[QKV_ELEMS];
__device__ __align__(16) __nv_bfloat16 g_kl[QKV_ELEMS];
__device__ __align__(16) __nv_bfloat16 g_vh[QKV_ELEMS];
__device__ __align__(16) __nv_bfloat16 g_vl[QKV_ELEMS];
__device__ __align__(16) __nv_bfloat16 g_ahi[(size_t)8192 * 1024];
__device__ __align__(16) __nv_bfloat16 g_alo[(size_t)8192 * 1024];
__device__ __align__(16) __nv_bfloat16 g_w1hi[(size_t)3072 * 1024];
__device__ __align__(16) __nv_bfloat16 g_w1lo[(size_t)3072 * 1024];
__device__ __align__(16) __nv_bfloat16 g_w2hi[(size_t)1024 * 1024];
__device__ __align__(16) __nv_bfloat16 g_w2lo[(size_t)1024 * 1024];
__device__ __align__(16) __nv_bfloat16 g_aohi[(size_t)8192 * 1024];
__device__ __align__(16) __nv_bfloat16 g_aolo[(size_t)8192 * 1024];

__device__ __forceinline__ uint32_t smem_to_u32(const void* p) {
    uint32_t a;
    asm("{ .reg .u64 t; cvta.to.shared.u64 t, %1; cvt.u32.u64 %0, t; }" : "=r"(a) : "l"(p));
    return a;
}
#define SWZ(o) ((o) ^ (((o) >> 3) & 0x70))

__device__ __forceinline__ void ldsm_x4(uint32_t* d, uint32_t addr) {
    asm volatile("ldmatrix.sync.aligned.m8n8.x4.shared.b16 {%0,%1,%2,%3}, [%4];"
                 : "=r"(d[0]), "=r"(d[1]), "=r"(d[2]), "=r"(d[3]) : "r"(addr));
}
__device__ __forceinline__ void ldsm_x4_t(uint32_t* d, uint32_t addr) {
    asm volatile("ldmatrix.sync.aligned.m8n8.x4.trans.shared.b16 {%0,%1,%2,%3}, [%4];"
                 : "=r"(d[0]), "=r"(d[1]), "=r"(d[2]), "=r"(d[3]) : "r"(addr));
}
__device__ __forceinline__ void mma_bf16(float* c, const uint32_t* a, uint32_t b0, uint32_t b1) {
    asm volatile(
        "mma.sync.aligned.m16n8k16.row.col.f32.bf16.bf16.f32 "
        "{%0,%1,%2,%3}, {%4,%5,%6,%7}, {%8,%9}, {%0,%1,%2,%3};"
        : "+f"(c[0]), "+f"(c[1]), "+f"(c[2]), "+f"(c[3])
        : "r"(a[0]), "r"(a[1]), "r"(a[2]), "r"(a[3]), "r"(b0), "r"(b1));
}
__device__ __forceinline__ void cp_async16(uint32_t sdst, const void* gsrc) {
    asm volatile("cp.async.cg.shared.global [%0], [%1], 16;" :: "r"(sdst), "l"(gsrc));
}
#define CP_COMMIT() asm volatile("cp.async.commit_group;" ::: "memory")
#define CP_WAIT_ALL() asm volatile("cp.async.wait_group 0;" ::: "memory")

// pack two floats into bf16x2 hi/lo error-split pairs (low half = first arg)
__device__ __forceinline__ void split2(float a, float b, uint32_t& hi2, uint32_t& lo2) {
    __nv_bfloat16 ah = __float2bfloat16_rn(a);
    __nv_bfloat16 bh = __float2bfloat16_rn(b);
    __nv_bfloat16 al = __float2bfloat16_rn(a - __bfloat162float(ah));
    __nv_bfloat16 bl = __float2bfloat16_rn(b - __bfloat162float(bh));
    __nv_bfloat162 h2; h2.x = ah; h2.y = bh;
    __nv_bfloat162 l2; l2.x = al; l2.y = bl;
    hi2 = *reinterpret_cast<uint32_t*>(&h2);
    lo2 = *reinterpret_cast<uint32_t*>(&l2);
}

// ---------------------------------------------------------------------------
// fp32 -> (bf16 hi, bf16 lo) split
// ---------------------------------------------------------------------------
__global__ __launch_bounds__(256) void split_bf16(
    const float* __restrict__ x, __nv_bfloat16* __restrict__ hi,
    __nv_bfloat16* __restrict__ lo, int n4)
{
    int i = blockIdx.x * 256 + threadIdx.x;
    if (i >= n4) return;
    float4 v = ((const float4*)x)[i];
    float vv[4] = {v.x, v.y, v.z, v.w};
    ushort4 h, l;
    unsigned short* hp = &h.x;
    unsigned short* lp = &l.x;
#pragma unroll
    for (int j = 0; j < 4; j++) {
        __nv_bfloat16 bh = __float2bfloat16_rn(vv[j]);
        __nv_bfloat16 bl = __float2bfloat16_rn(vv[j] - __bfloat162float(bh));
        hp[j] = *reinterpret_cast<unsigned short*>(&bh);
        lp[j] = *reinterpret_cast<unsigned short*>(&bl);
    }
    ((ushort4*)hi)[i] = h;
    ((ushort4*)lo)[i] = l;
}

// ---------------------------------------------------------------------------
// HMMA bf16-split GEMM (NT), K=1024, 128x128 tile, 8 warps.
// BK=32, two stages packed side-by-side in 128B swizzled rows -> 64KB smem,
// 2 CTAs/SM. One __syncthreads per chunk.
// MODE 0: scatter q/k/v bf16 hi/lo head-major; q scaled 0.125
// MODE 1: C = acc + bias[n] -> fp32 out
// ---------------------------------------------------------------------------
#define GEMM_SMEM 65536

template <int MODE>
__global__ __launch_bounds__(256, 2)
void gemm_hmma(const __nv_bfloat16* __restrict__ Ah, const __nv_bfloat16* __restrict__ Al,
               const __nv_bfloat16* __restrict__ Bh, const __nv_bfloat16* __restrict__ Bl,
               const float* __restrict__ bias, float* __restrict__ C, int ldc,
               __nv_bfloat16* __restrict__ OQH, __nv_bfloat16* __restrict__ OQL,
               __nv_bfloat16* __restrict__ OKH, __nv_bfloat16* __restrict__ OKL,
               __nv_bfloat16* __restrict__ OVH, __nv_bfloat16* __restrict__ OVL)
{
    extern __shared__ char smem[];
    const uint32_t sb = smem_to_u32(smem);
    const int tid = threadIdx.x;
    const int wid = tid >> 5, lane = tid & 31;
    const int bm = blockIdx.y * 128, bn = blockIdx.x * 128;
    const int wm = wid >> 1, wn = wid & 1;

    const __nv_bfloat16* tb[4] = {
        Ah + (size_t)bm * 1024, Al + (size_t)bm * 1024,
        Bh + (size_t)bn * 1024, Bl + (size_t)bn * 1024 };

    // loader mapping: each thread does 2 x 16B per tile per stage
    const int lr = tid >> 1;                 // row 0..127
    const int lc0 = (tid & 1) * 2;           // 16B chunk base 0 or 2

    const int q = lane >> 3, l8 = lane & 7;
    const int ar = wm * 32 + (q & 1) * 8 + l8;    // + mt*16
    const int ac = (q >> 1) * 16;                 // byte offset within 32B k16
    const int br = wn * 64 + (q >> 1) * 8 + l8;   // + jp*16
    const int bc = (q & 1) * 16;

    float acc[2][8][4];
#pragma unroll
    for (int mt = 0; mt < 2; mt++)
#pragma unroll
        for (int nt = 0; nt < 8; nt++)
#pragma unroll
            for (int e = 0; e < 4; e++) acc[mt][nt][e] = 0.f;

    // stage s occupies column bytes [s*64, s*64+64) of the 128B rows
#define ISSUE(kc_, s_) do {                                                       \
    _Pragma("unroll")                                                             \
    for (int t = 0; t < 4; t++) {                                                 \
        const __nv_bfloat16* gp = tb[t] + (size_t)(kc_) * 32 + lc0 * 8;           \
        const uint32_t tbase = sb + (uint32_t)t * 16384u;                         \
        _Pragma("unroll")                                                         \
        for (int i2 = 0; i2 < 2; i2++)                                            \
            cp_async16(tbase + SWZ((uint32_t)(lr * 128 + (s_) * 64 + (lc0 + i2) * 16)), \
                       gp + (size_t)lr * 1024 + i2 * 8);                          \
    }                                                                             \
    CP_COMMIT();                                                                  \
} while (0)

    ISSUE(0, 0);

    for (int kc = 0; kc < 32; kc++) {
        const int s = kc & 1;
        CP_WAIT_ALL();
        __syncthreads();
        if (kc < 31) ISSUE(kc + 1, s ^ 1);

        const uint32_t sAh = sb, sAl = sb + 16384u;
        const uint32_t sBh = sb + 32768u, sBl = sb + 49152u;
        const uint32_t scol = (uint32_t)s * 64u;

#pragma unroll
        for (int ks = 0; ks < 2; ks++) {
            uint32_t ah[2][4], al[2][4];
#pragma unroll
            for (int mt = 0; mt < 2; mt++) {
                const uint32_t off =
                    SWZ((uint32_t)((ar + mt * 16) * 128) + scol + ks * 32 + ac);
                ldsm_x4(ah[mt], sAh + off);
                ldsm_x4(al[mt], sAl + off);
            }
#pragma unroll
            for (int jp = 0; jp < 4; jp++) {
                uint32_t bh[4], bl[4];
                const uint32_t off =
                    SWZ((uint32_t)((br + jp * 16) * 128) + scol + ks * 32 + bc);
                ldsm_x4(bh, sBh + off);
                ldsm_x4(bl, sBl + off);
#pragma unroll
                for (int mt = 0; mt < 2; mt++) {
                    mma_bf16(acc[mt][2 * jp + 0], ah[mt], bh[0], bh[1]);
                    mma_bf16(acc[mt][2 * jp + 1], ah[mt], bh[2], bh[3]);
                    mma_bf16(acc[mt][2 * jp + 0], ah[mt], bl[0], bl[1]);
                    mma_bf16(acc[mt][2 * jp + 1], ah[mt], bl[2], bl[3]);
                    mma_bf16(acc[mt][2 * jp + 0], al[mt], bh[0], bh[1]);
                    mma_bf16(acc[mt][2 * jp + 1], al[mt], bh[2], bh[3]);
                }
            }
        }
    }
#undef ISSUE

    const int g = lane >> 2, tg = lane & 3;
    if (MODE == 0) {
        const int which = bn >> 10;
        __nv_bfloat16* dh = (which == 0) ? OQH : ((which == 1) ? OKH : OVH);
        __nv_bfloat16* dl = (which == 0) ? OQL : ((which == 1) ? OKL : OVL);
        const float sc = (which == 0) ? 0.125f : 1.0f;
#pragma unroll
        for (int mt = 0; mt < 2; mt++) {
            const int row0 = bm + wm * 32 + mt * 16 + g;
            const int bidx = row0 >> 10, tt = row0 & 1023;
#pragma unroll
            for (int nt = 0; nt < 8; nt++) {
                const int col = bn + wn * 64 + nt * 8 + tg * 2;
                const int e = col & 1023, hh = e >> 6, dd = e & 63;
                const size_t i0 = (((size_t)bidx * 16 + hh) * 1024 + tt) * 64 + dd;
                uint32_t h2, l2;
                split2(acc[mt][nt][0] * sc, acc[mt][nt][1] * sc, h2, l2);
                *(uint32_t*)(dh + i0) = h2;
                *(uint32_t*)(dl + i0) = l2;
                split2(acc[mt][nt][2] * sc, acc[mt][nt][3] * sc, h2, l2);
                *(uint32_t*)(dh + i0 + 8 * 64) = h2;
                *(uint32_t*)(dl + i0 + 8 * 64) = l2;
            }
        }
    } else {
#pragma unroll
        for (int mt = 0; mt < 2; mt++) {
            const int row0 = bm + wm * 32 + mt * 16 + g;
#pragma unroll
            for (int nt = 0; nt < 8; nt++) {
                const int col = bn + wn * 64 + nt * 8 + tg * 2;
                const float b0v = bias[col], b1v = bias[col + 1];
                *(float2*)(C + (size_t)row0 * ldc + col) =
                    make_float2(acc[mt][nt][0] + b0v, acc[mt][nt][1] + b1v);
                *(float2*)(C + (size_t)(row0 + 8) * ldc + col) =
                    make_float2(acc[mt][nt][2] + b0v, acc[mt][nt][3] + b1v);
            }
        }
    }
}

// ---------------------------------------------------------------------------
// Tensor-core flash attention, bf16 3-term splits for QK^T and PV.
// One CTA per (bh, 128-query tile). 8 warps. 2 CTAs/SM.
// smem: bias 4KB | Qh/Ql 32KB | KV double buffer 2x32KB = 102400 B.
// ---------------------------------------------------------------------------
#define AT_QOFF 4096u
#define AT_KVOFF 36864u
#define AT_SMEM (4096 + 32768 + 65536)

__global__ __launch_bounds__(256, 2) void attn_tc(
    const __nv_bfloat16* __restrict__ qh_, const __nv_bfloat16* __restrict__ ql_,
    const __nv_bfloat16* __restrict__ kh_, const __nv_bfloat16* __restrict__ kl_,
    const __nv_bfloat16* __restrict__ vh_, const __nv_bfloat16* __restrict__ vl_,
    const float* __restrict__ biases,
    __nv_bfloat16* __restrict__ aohi, __nv_bfloat16* __restrict__ aolo)
{
    extern __shared__ char smem[];
    const uint32_t sb = smem_to_u32(smem);
    const int tid = threadIdx.x, wid = tid >> 5, lane = tid & 31;
    const int g = lane >> 2, tg = lane & 3, qq = lane >> 3, l8 = lane & 7;
    const int qi = blockIdx.x, bh = blockIdx.y;
    const int b = bh >> 4, h = bh & 15;
    const int m0 = wid * 16;
    const size_t hb = (size_t)bh << 16;

    float* bias_s = (float*)smem;
    for (int i = tid; i < 1024; i += 256) bias_s[i] = biases[h * 1024 + i];

    {
        const __nv_bfloat16* srcs[2] = { qh_ + hb + (size_t)(qi * 128) * 64,
                                         ql_ + hb + (size_t)(qi * 128) * 64 };
#pragma unroll
        for (int t = 0; t < 2; t++)
#pragma unroll
            for (int i2 = 0; i2 < 4; i2++) {
                const int idx = tid + 256 * i2;
                const int r = idx >> 3, c = idx & 7;
                cp_async16(sb + AT_QOFF + t * 16384u + SWZ((uint32_t)(r * 128 + c * 16)),
                           srcs[t] + (size_t)r * 64 + c * 8);
            }
        CP_COMMIT();
    }

    const __nv_bfloat16* kvp[4] = { kh_ + hb, kl_ + hb, vh_ + hb, vl_ + hb };

#define ISSUE_KV(kt_, buf_) do {                                                  \
    const uint32_t st = sb + AT_KVOFF + (uint32_t)(buf_) * 32768u;                \
    _Pragma("unroll")                                                             \
    for (int t = 0; t < 4; t++) {                                                 \
        const __nv_bfloat16* gp = kvp[t] + (size_t)((kt_) * 64) * 64;             \
        _Pragma("unroll")                                                         \
        for (int i2 = 0; i2 < 2; i2++) {                                          \
            const int idx = tid + 256 * i2;                                       \
            const int r = idx >> 3, c = idx & 7;                                  \
            cp_async16(st + t * 8192u + SWZ((uint32_t)(r * 128 + c * 16)),        \
                       gp + (size_t)r * 64 + c * 8);                              \
        }                                                                         \
    }                                                                             \
    CP_COMMIT();                                                                  \
} while (0)

    ISSUE_KV(0, 0);
    CP_WAIT_ALL();
    __syncthreads();

    uint32_t qfh[4][4], qfl[4][4];
#pragma unroll
    for (int ks = 0; ks < 4; ks++) {
        const uint32_t off =
            SWZ((uint32_t)((m0 + (qq & 1) * 8 + l8) * 128 + (qq >> 1) * 16 + ks * 32));
        ldsm_x4(qfh[ks], sb + AT_QOFF + off);
        ldsm_x4(qfl[ks], sb + AT_QOFF + 16384u + off);
    }

    float O[8][4];
#pragma unroll
    for (int dt = 0; dt < 8; dt++)
#pragma unroll
        for (int e = 0; e < 4; e++) O[dt][e] = 0.f;
    float mr0 = -1e30f, mr1 = -1e30f, lr0 = 0.f, lr1 = 0.f;

    const int i0 = qi * 128 + m0 + g;
    const int ir0 = i0 >> 5, ic0 = i0 & 31;
    const int ir1 = (i0 + 8) >> 5, ic1 = (i0 + 8) & 31;

    for (int kt = 0; kt < 16; kt++) {
        if (kt > 0) { CP_WAIT_ALL(); __syncthreads(); }
        if (kt < 15) ISSUE_KV(kt + 1, (kt + 1) & 1);
        const uint32_t kb = sb + AT_KVOFF + (uint32_t)(kt & 1) * 32768u;

        float s[8][4];
#pragma unroll
        for (int t = 0; t < 8; t++)
#pragma unroll
            for (int e = 0; e < 4; e++) s[t][e] = 0.f;

#pragma unroll
        for (int ks = 0; ks < 4; ks++) {
#pragma unroll
            for (int jp = 0; jp < 4; jp++) {
                uint32_t khf[4], klf[4];
                const uint32_t off = SWZ((uint32_t)(
                    ((qq >> 1) * 8 + l8 + jp * 16) * 128 + (qq & 1) * 16 + ks * 32));
                ldsm_x4(khf, kb + off);
                ldsm_x4(klf, kb + 8192u + off);
                mma_bf16(s[2 * jp + 0], qfh[ks], khf[0], khf[1]);
                mma_bf16(s[2 * jp + 1], qfh[ks], khf[2], khf[3]);
                mma_bf16(s[2 * jp + 0], qfh[ks], klf[0], klf[1]);
                mma_bf16(s[2 * jp + 1], qfh[ks], klf[2], klf[3]);
                mma_bf16(s[2 * jp + 0], qfl[ks], khf[0], khf[1]);
                mma_bf16(s[2 * jp + 1], qfl[ks], khf[2], khf[3]);
            }
        }

#pragma unroll
        for (int t = 0; t < 8; t++) {
            const int j0 = kt * 64 + t * 8 + tg * 2;
            const int jr0 = j0 >> 5, jc0 = j0 & 31;
            const int jr1 = (j0 + 1) >> 5, jc1 = (j0 + 1) & 31;
            s[t][0] += bias_s[abs(ir0 - jr0) * 32 + abs(ic0 - jc0)];
            s[t][1] += bias_s[abs(ir0 - jr1) * 32 + abs(ic0 - jc1)];
            s[t][2] += bias_s[abs(ir1 - jr0) * 32 + abs(ic1 - jc0)];
            s[t][3] += bias_s[abs(ir1 - jr1) * 32 + abs(ic1 - jc1)];
        }

        float mx0 = -1e30f, mx1 = -1e30f;
#pragma unroll
        for (int t = 0; t < 8; t++) {
            mx0 = fmaxf(mx0, fmaxf(s[t][0], s[t][1]));
            mx1 = fmaxf(mx1, fmaxf(s[t][2], s[t][3]));
        }
        mx0 = fmaxf(mx0, __shfl_xor_sync(0xffffffffu, mx0, 1));
        mx0 = fmaxf(mx0, __shfl_xor_sync(0xffffffffu, mx0, 2));
        mx1 = fmaxf(mx1, __shfl_xor_sync(0xffffffffu, mx1, 1));
        mx1 = fmaxf(mx1, __shfl_xor_sync(0xffffffffu, mx1, 2));
        const float mn0 = fmaxf(mr0, mx0), mn1 = fmaxf(mr1, mx1);
        const float a0 = __expf(mr0 - mn0), a1 = __expf(mr1 - mn1);
        mr0 = mn0; mr1 = mn1;
        float sum0 = 0.f, sum1 = 0.f;
#pragma unroll
        for (int t = 0; t < 8; t++) {
            s[t][0] = __expf(s[t][0] - mn0); sum0 += s[t][0];
            s[t][1] = __expf(s[t][1] - mn0); sum0 += s[t][1];
            s[t][2] = __expf(s[t][2] - mn1); sum1 += s[t][2];
            s[t][3] = __expf(s[t][3] - mn1); sum1 += s[t][3];
        }
        sum0 += __shfl_xor_sync(0xffffffffu, sum0, 1);
        sum0 += __shfl_xor_sync(0xffffffffu, sum0, 2);
        sum1 += __shfl_xor_sync(0xffffffffu, sum1, 1);
        sum1 += __shfl_xor_sync(0xffffffffu, sum1, 2);
        lr0 = lr0 * a0 + sum0;
        lr1 = lr1 * a1 + sum1;
#pragma unroll
        for (int dt = 0; dt < 8; dt++) {
            O[dt][0] *= a0; O[dt][1] *= a0;
            O[dt][2] *= a1; O[dt][3] *= a1;
        }

#pragma unroll
        for (int js = 0; js < 4; js++) {
            uint32_t aph[4], apl[4];
            split2(s[2 * js][0],     s[2 * js][1],     aph[0], apl[0]);
            split2(s[2 * js][2],     s[2 * js][3],     aph[1], apl[1]);
            split2(s[2 * js + 1][0], s[2 * js + 1][1], aph[2], apl[2]);
            split2(s[2 * js + 1][2], s[2 * js + 1][3], aph[3], apl[3]);
#pragma unroll
            for (int dp = 0; dp < 4; dp++) {
                uint32_t vhf[4], vlf[4];
                const uint32_t off = SWZ((uint32_t)(
                    (js * 16 + (qq & 1) * 8 + l8) * 128 + dp * 32 + (qq >> 1) * 16));
                ldsm_x4_t(vhf, kb + 16384u + off);
                ldsm_x4_t(vlf, kb + 24576u + off);
                mma_bf16(O[2 * dp + 0], aph, vhf[0], vhf[1]);
                mma_bf16(O[2 * dp + 1], aph, vhf[2], vhf[3]);
                mma_bf16(O[2 * dp + 0], aph, vlf[0], vlf[1]);
                mma_bf16(O[2 * dp + 1], aph, vlf[2], vlf[3]);
                mma_bf16(O[2 * dp + 0], apl, vhf[0], vhf[1]);
                mma_bf16(O[2 * dp + 1], apl, vhf[2], vhf[3]);
            }
        }
    }
#undef ISSUE_KV

    const float inv0 = 1.f / lr0, inv1 = 1.f / lr1;
    const int t0 = qi * 128 + m0 + g;
    const size_t base0 = ((size_t)(b * 1024 + t0)) * 1024 + h * 64;
    const size_t base1 = base0 + 8 * 1024;
#pragma unroll
    for (int dt = 0; dt < 8; dt++) {
        const int d0 = dt * 8 + tg * 2;
        uint32_t h2, l2;
        split2(O[dt][0] * inv0, O[dt][1] * inv0, h2, l2);
        *(uint32_t*)(aohi + base0 + d0) = h2;
        *(uint32_t*)(aolo + base0 + d0) = l2;
        split2(O[dt][2] * inv1, O[dt][3] * inv1, h2, l2);
        *(uint32_t*)(aohi + base1 + d0) = h2;
        *(uint32_t*)(aolo + base1 + d0) = l2;
    }
}

// ---------------------------------------------------------------------------
extern "C" void kernel_launch(void* const* d_in, const int* in_sizes, int n_in,
                              void* d_out, int out_size)
{
    (void)in_sizes; (void)n_in; (void)out_size;
    const float* x      = (const float*)d_in[0];
    const float* w_qkv  = (const float*)d_in[1];
    const float* biases = (const float*)d_in[2];
    const float* w_out  = (const float*)d_in[4];
    const float* b_out  = (const float*)d_in[5];
    float* out = (float*)d_out;

    __nv_bfloat16 *qh, *ql, *kh, *kl, *vh, *vl;
    __nv_bfloat16 *ahi, *alo, *w1hi, *w1lo, *w2hi, *w2lo, *aohi, *aolo;
    cudaGetSymbolAddress((void**)&qh, g_qh);
    cudaGetSymbolAddress((void**)&ql, g_ql);
    cudaGetSymbolAddress((void**)&kh, g_kh);
    cudaGetSymbolAddress((void**)&kl, g_kl);
    cudaGetSymbolAddress((void**)&vh, g_vh);
    cudaGetSymbolAddress((void**)&vl, g_vl);
    cudaGetSymbolAddress((void**)&ahi, g_ahi);
    cudaGetSymbolAddress((void**)&alo, g_alo);
    cudaGetSymbolAddress((void**)&w1hi, g_w1hi);
    cudaGetSymbolAddress((void**)&w1lo, g_w1lo);
    cudaGetSymbolAddress((void**)&w2hi, g_w2hi);
    cudaGetSymbolAddress((void**)&w2lo, g_w2lo);
    cudaGetSymbolAddress((void**)&aohi, g_aohi);
    cudaGetSymbolAddress((void**)&aolo, g_aolo);

    cudaFuncSetAttribute(gemm_hmma<0>, cudaFuncAttributeMaxDynamicSharedMemorySize, GEMM_SMEM);
    cudaFuncSetAttribute(gemm_hmma<1>, cudaFuncAttributeMaxDynamicSharedMemorySize, GEMM_SMEM);
    cudaFuncSetAttribute(attn_tc, cudaFuncAttributeMaxDynamicSharedMemorySize, AT_SMEM);

    // 1) bf16 hi/lo splits of inputs
    split_bf16<<<8192, 256>>>(x, ahi, alo, 8192 * 1024 / 4);
    split_bf16<<<3072, 256>>>(w_qkv, w1hi, w1lo, 3072 * 1024 / 4);
    split_bf16<<<1024, 256>>>(w_out, w2hi, w2lo, 1024 * 1024 / 4);

    // 2) QKV projection -> head-major bf16 hi/lo q/k/v (q pre-scaled)
    {
        dim3 grid(3072 / 128, 8192 / 128);
        gemm_hmma<0><<<grid, 256, GEMM_SMEM>>>(ahi, alo, w1hi, w1lo, nullptr, nullptr, 0,
                                               qh, ql, kh, kl, vh, vl);
    }

    // 3) Tensor-core flash attention -> aohi/aolo
    {
        dim3 grid(8, 128);
        attn_tc<<<grid, 256, AT_SMEM>>>(qh, ql, kh, kl, vh, vl, biases, aohi, aolo);
    }

    // 4) Output projection + bias -> fp32 out
    {
        dim3 grid(1024 / 128, 8192 / 128);
        gemm_hmma<1><<<grid, 256, GEMM_SMEM>>>(aohi, aolo, w2hi, w2lo, b_out, out, 1024,
                                               nullptr, nullptr, nullptr, nullptr, nullptr, nullptr);
    }
}

// round 6
// speedup vs baseline: 1.1395x; 1.1395x over previous
#include <cuda_runtime.h>
#include <cuda_bf16.h>
#include <cstdint>

#define B_ 8
#define N_ 1024
#define E_ 1024
#define H_ 16
#define D_ 64

// ---------------------------------------------------------------------------
// Static scratch (allocation-free)
// ---------------------------------------------------------------------------
#define QKV_ELEMS ((size_t)B_ * H_ * N_ * D_)
__device__ __align__(16) __nv_bfloat16 g_qh[QKV_ELEMS];
__device__ __align__(16) __nv_bfloat16 g_ql[QKV_ELEMS];
__device__ __align__(16) __nv_bfloat16 g_kh[QKV_ELEMS];
__device__ __align__(16) __nv_bfloat16 g_kl[QKV_ELEMS];
__device__ __align__(16) __nv_bfloat16 g_vh[QKV_ELEMS];
__device__ __align__(16) __nv_bfloat16 g_vl[QKV_ELEMS];
__device__ __align__(16) __nv_bfloat16 g_ahi[(size_t)8192 * 1024];
__device__ __align__(16) __nv_bfloat16 g_alo[(size_t)8192 * 1024];
__device__ __align__(16) __nv_bfloat16 g_w1hi[(size_t)3072 * 1024];
__device__ __align__(16) __nv_bfloat16 g_w1lo[(size_t)3072 * 1024];
__device__ __align__(16) __nv_bfloat16 g_w2hi[(size_t)1024 * 1024];
__device__ __align__(16) __nv_bfloat16 g_w2lo[(size_t)1024 * 1024];
__device__ __align__(16) __nv_bfloat16 g_aohi[(size_t)8192 * 1024];
__device__ __align__(16) __nv_bfloat16 g_aolo[(size_t)8192 * 1024];

__device__ __forceinline__ uint32_t smem_to_u32(const void* p) {
    uint32_t a;
    asm("{ .reg .u64 t; cvta.to.shared.u64 t, %1; cvt.u32.u64 %0, t; }" : "=r"(a) : "l"(p));
    return a;
}
#define SWZ(o) ((o) ^ (((o) >> 3) & 0x70))

__device__ __forceinline__ void ldsm_x4(uint32_t* d, uint32_t addr) {
    asm volatile("ldmatrix.sync.aligned.m8n8.x4.shared.b16 {%0,%1,%2,%3}, [%4];"
                 : "=r"(d[0]), "=r"(d[1]), "=r"(d[2]), "=r"(d[3]) : "r"(addr));
}
__device__ __forceinline__ void ldsm_x4_t(uint32_t* d, uint32_t addr) {
    asm volatile("ldmatrix.sync.aligned.m8n8.x4.trans.shared.b16 {%0,%1,%2,%3}, [%4];"
                 : "=r"(d[0]), "=r"(d[1]), "=r"(d[2]), "=r"(d[3]) : "r"(addr));
}
__device__ __forceinline__ void mma_bf16(float* c, const uint32_t* a, uint32_t b0, uint32_t b1) {
    asm volatile(
        "mma.sync.aligned.m16n8k16.row.col.f32.bf16.bf16.f32 "
        "{%0,%1,%2,%3}, {%4,%5,%6,%7}, {%8,%9}, {%0,%1,%2,%3};"
        : "+f"(c[0]), "+f"(c[1]), "+f"(c[2]), "+f"(c[3])
        : "r"(a[0]), "r"(a[1]), "r"(a[2]), "r"(a[3]), "r"(b0), "r"(b1));
}
__device__ __forceinline__ void cp_async16(uint32_t sdst, const void* gsrc) {
    asm volatile("cp.async.cg.shared.global [%0], [%1], 16;" :: "r"(sdst), "l"(gsrc));
}
#define CP_COMMIT() asm volatile("cp.async.commit_group;" ::: "memory")
#define CP_WAIT_ALL() asm volatile("cp.async.wait_group 0;" ::: "memory")

// pack two floats into bf16x2 hi/lo error-split pairs
__device__ __forceinline__ void split2(float a, float b, uint32_t& hi2, uint32_t& lo2) {
    __nv_bfloat16 ah = __float2bfloat16_rn(a);
    __nv_bfloat16 bh = __float2bfloat16_rn(b);
    __nv_bfloat16 al = __float2bfloat16_rn(a - __bfloat162float(ah));
    __nv_bfloat16 bl = __float2bfloat16_rn(b - __bfloat162float(bh));
    __nv_bfloat162 h2; h2.x = ah; h2.y = bh;
    __nv_bfloat162 l2; l2.x = al; l2.y = bl;
    hi2 = *reinterpret_cast<uint32_t*>(&h2);
    lo2 = *reinterpret_cast<uint32_t*>(&l2);
}

// ---------------------------------------------------------------------------
// fp32 -> (bf16 hi, bf16 lo) split
// ---------------------------------------------------------------------------
__global__ __launch_bounds__(256) void split_bf16(
    const float* __restrict__ x, __nv_bfloat16* __restrict__ hi,
    __nv_bfloat16* __restrict__ lo, int n4)
{
    int i = blockIdx.x * 256 + threadIdx.x;
    if (i >= n4) return;
    float4 v = ((const float4*)x)[i];
    float vv[4] = {v.x, v.y, v.z, v.w};
    ushort4 h, l;
    unsigned short* hp = &h.x;
    unsigned short* lp = &l.x;
#pragma unroll
    for (int j = 0; j < 4; j++) {
        __nv_bfloat16 bh = __float2bfloat16_rn(vv[j]);
        __nv_bfloat16 bl = __float2bfloat16_rn(vv[j] - __bfloat162float(bh));
        hp[j] = *reinterpret_cast<unsigned short*>(&bh);
        lp[j] = *reinterpret_cast<unsigned short*>(&bl);
    }
    ((ushort4*)hi)[i] = h;
    ((ushort4*)lo)[i] = l;
}

// ---------------------------------------------------------------------------
// GEMM1 (QKV projection): 128x256 tile, 512 threads (16 warps, 4/SMSP), BK=64,
// double-buffered 2x96KB smem, 1 CTA/SM. 3-term bf16 split.
// Scatters q/k/v bf16 hi/lo head-major, q scaled by 0.125.
// ---------------------------------------------------------------------------
#define G1_STAGE 98304u
#define G1_SMEM (2 * 98304)

__global__ __launch_bounds__(512, 1)
void gemm1_hmma(const __nv_bfloat16* __restrict__ Ah, const __nv_bfloat16* __restrict__ Al,
                const __nv_bfloat16* __restrict__ Bh, const __nv_bfloat16* __restrict__ Bl,
                __nv_bfloat16* __restrict__ OQH, __nv_bfloat16* __restrict__ OQL,
                __nv_bfloat16* __restrict__ OKH, __nv_bfloat16* __restrict__ OKL,
                __nv_bfloat16* __restrict__ OVH, __nv_bfloat16* __restrict__ OVL)
{
    extern __shared__ char smem[];
    const uint32_t sb = smem_to_u32(smem);
    const int tid = threadIdx.x;
    const int wid = tid >> 5, lane = tid & 31;
    const int bm = blockIdx.y * 128, bn = blockIdx.x * 256;
    const int wm = wid >> 2, wn = wid & 3;   // 4x4 warp grid

    const __nv_bfloat16* tA[2] = { Ah + (size_t)bm * 1024, Al + (size_t)bm * 1024 };
    const __nv_bfloat16* tB[2] = { Bh + (size_t)bn * 1024, Bl + (size_t)bn * 1024 };

    const int q = lane >> 3, l8 = lane & 7;
    const int ar = wm * 32 + (q & 1) * 8 + l8;    // + mt*16
    const int ac = (q >> 1) * 16;
    const int br = wn * 64 + (q >> 1) * 8 + l8;   // + jp*16
    const int bc = (q & 1) * 16;

    float acc[2][8][4];
#pragma unroll
    for (int mt = 0; mt < 2; mt++)
#pragma unroll
        for (int nt = 0; nt < 8; nt++)
#pragma unroll
            for (int e = 0; e < 4; e++) acc[mt][nt][e] = 0.f;

#define ISSUE1(kc_, buf_) do {                                                    \
    const uint32_t stage = sb + (uint32_t)(buf_) * G1_STAGE;                      \
    _Pragma("unroll")                                                             \
    for (int t = 0; t < 2; t++) {                                                 \
        const __nv_bfloat16* gp = tA[t] + (size_t)(kc_) * 64;                     \
        _Pragma("unroll")                                                         \
        for (int i2 = 0; i2 < 2; i2++) {                                          \
            const int idx = tid + 512 * i2;                                       \
            const int r = idx >> 3, c = idx & 7;                                  \
            cp_async16(stage + t * 16384u + SWZ((uint32_t)(r * 128 + c * 16)),    \
                       gp + (size_t)r * 1024 + c * 8);                            \
        }                                                                         \
    }                                                                             \
    _Pragma("unroll")                                                             \
    for (int t = 0; t < 2; t++) {                                                 \
        const __nv_bfloat16* gp = tB[t] + (size_t)(kc_) * 64;                     \
        _Pragma("unroll")                                                         \
        for (int i2 = 0; i2 < 4; i2++) {                                          \
            const int idx = tid + 512 * i2;                                       \
            const int r = idx >> 3, c = idx & 7;                                  \
            cp_async16(stage + 32768u + t * 32768u + SWZ((uint32_t)(r * 128 + c * 16)), \
                       gp + (size_t)r * 1024 + c * 8);                            \
        }                                                                         \
    }                                                                             \
    CP_COMMIT();                                                                  \
} while (0)

    ISSUE1(0, 0);

    for (int kc = 0; kc < 16; kc++) {
        const int buf = kc & 1;
        CP_WAIT_ALL();
        __syncthreads();
        if (kc < 15) ISSUE1(kc + 1, buf ^ 1);

        const uint32_t stage = sb + (uint32_t)buf * G1_STAGE;
        const uint32_t sAh = stage, sAl = stage + 16384u;
        const uint32_t sBh = stage + 32768u, sBl = stage + 65536u;

#pragma unroll
        for (int ks = 0; ks < 4; ks++) {
            uint32_t ah[2][4], al[2][4];
#pragma unroll
            for (int mt = 0; mt < 2; mt++) {
                const uint32_t off = SWZ((uint32_t)((ar + mt * 16) * 128 + ac + ks * 32));
                ldsm_x4(ah[mt], sAh + off);
                ldsm_x4(al[mt], sAl + off);
            }
#pragma unroll
            for (int jp = 0; jp < 4; jp++) {
                uint32_t bh[4], bl[4];
                const uint32_t off = SWZ((uint32_t)((br + jp * 16) * 128 + bc + ks * 32));
                ldsm_x4(bh, sBh + off);
                ldsm_x4(bl, sBl + off);
#pragma unroll
                for (int mt = 0; mt < 2; mt++) {
                    mma_bf16(acc[mt][2 * jp + 0], ah[mt], bh[0], bh[1]);
                    mma_bf16(acc[mt][2 * jp + 1], ah[mt], bh[2], bh[3]);
                    mma_bf16(acc[mt][2 * jp + 0], ah[mt], bl[0], bl[1]);
                    mma_bf16(acc[mt][2 * jp + 1], ah[mt], bl[2], bl[3]);
                    mma_bf16(acc[mt][2 * jp + 0], al[mt], bh[0], bh[1]);
                    mma_bf16(acc[mt][2 * jp + 1], al[mt], bh[2], bh[3]);
                }
            }
        }
    }
#undef ISSUE1

    const int g = lane >> 2, tg = lane & 3;
    const int which = bn >> 10;
    __nv_bfloat16* dh = (which == 0) ? OQH : ((which == 1) ? OKH : OVH);
    __nv_bfloat16* dl = (which == 0) ? OQL : ((which == 1) ? OKL : OVL);
    const float sc = (which == 0) ? 0.125f : 1.0f;
#pragma unroll
    for (int mt = 0; mt < 2; mt++) {
        const int row0 = bm + wm * 32 + mt * 16 + g;
        const int bidx = row0 >> 10, tt = row0 & 1023;
#pragma unroll
        for (int nt = 0; nt < 8; nt++) {
            const int col = bn + wn * 64 + nt * 8 + tg * 2;
            const int e = col & 1023, hh = e >> 6, dd = e & 63;
            const size_t i0 = (((size_t)bidx * 16 + hh) * 1024 + tt) * 64 + dd;
            uint32_t h2, l2;
            split2(acc[mt][nt][0] * sc, acc[mt][nt][1] * sc, h2, l2);
            *(uint32_t*)(dh + i0) = h2;
            *(uint32_t*)(dl + i0) = l2;
            split2(acc[mt][nt][2] * sc, acc[mt][nt][3] * sc, h2, l2);
            *(uint32_t*)(dh + i0 + 8 * 64) = h2;
            *(uint32_t*)(dl + i0 + 8 * 64) = l2;
        }
    }
}

// ---------------------------------------------------------------------------
// GEMM2 (output projection): round-4 proven 128x128, 256 threads, BK=64.
// C = acc + bias[n] -> fp32 out.
// ---------------------------------------------------------------------------
#define STAGE_BYTES 65536
#define GEMM_SMEM (2 * STAGE_BYTES)

__global__ __launch_bounds__(256, 1)
void gemm2_hmma(const __nv_bfloat16* __restrict__ Ah, const __nv_bfloat16* __restrict__ Al,
                const __nv_bfloat16* __restrict__ Bh, const __nv_bfloat16* __restrict__ Bl,
                const float* __restrict__ bias, float* __restrict__ C, int ldc)
{
    extern __shared__ char smem[];
    const uint32_t sb = smem_to_u32(smem);
    const int tid = threadIdx.x;
    const int wid = tid >> 5, lane = tid & 31;
    const int bm = blockIdx.y * 128, bn = blockIdx.x * 128;
    const int wm = wid >> 1, wn = wid & 1;

    const __nv_bfloat16* tb[4] = {
        Ah + (size_t)bm * 1024, Al + (size_t)bm * 1024,
        Bh + (size_t)bn * 1024, Bl + (size_t)bn * 1024 };

    const int rb = tid >> 3;
    const int cg = tid & 7;
    uint32_t soff[4];
#pragma unroll
    for (int it = 0; it < 4; it++)
        soff[it] = SWZ((uint32_t)((rb + it * 32) * 128 + cg * 16));

    const int q = lane >> 3, l8 = lane & 7;
    const int ar = wm * 32 + (q & 1) * 8 + l8;
    const int ac = (q >> 1) * 16;
    const int br = wn * 64 + (q >> 1) * 8 + l8;
    const int bc = (q & 1) * 16;

    float acc[2][8][4];
#pragma unroll
    for (int mt = 0; mt < 2; mt++)
#pragma unroll
        for (int nt = 0; nt < 8; nt++)
#pragma unroll
            for (int e = 0; e < 4; e++) acc[mt][nt][e] = 0.f;

#define ISSUE2(kc_, buf_) do {                                                  \
    const uint32_t stage = sb + (uint32_t)(buf_) * STAGE_BYTES;                 \
    _Pragma("unroll")                                                           \
    for (int t = 0; t < 4; t++) {                                               \
        const __nv_bfloat16* gp = tb[t] + (size_t)(kc_) * 64 + cg * 8;          \
        const uint32_t tbase = stage + (uint32_t)t * 16384u;                    \
        _Pragma("unroll")                                                       \
        for (int it = 0; it < 4; it++)                                          \
            cp_async16(tbase + soff[it], gp + (size_t)(rb + it * 32) * 1024);   \
    }                                                                           \
    CP_COMMIT();                                                                \
} while (0)

    ISSUE2(0, 0);

    for (int kc = 0; kc < 16; kc++) {
        const int buf = kc & 1;
        CP_WAIT_ALL();
        __syncthreads();
        if (kc < 15) ISSUE2(kc + 1, buf ^ 1);

        const uint32_t stage = sb + (uint32_t)buf * STAGE_BYTES;
        const uint32_t sAh = stage, sAl = stage + 16384u;
        const uint32_t sBh = stage + 32768u, sBl = stage + 49152u;

#pragma unroll
        for (int ks = 0; ks < 4; ks++) {
            uint32_t ah[2][4], al[2][4];
#pragma unroll
            for (int mt = 0; mt < 2; mt++) {
                const uint32_t off = SWZ((uint32_t)((ar + mt * 16) * 128 + ac + ks * 32));
                ldsm_x4(ah[mt], sAh + off);
                ldsm_x4(al[mt], sAl + off);
            }
#pragma unroll
            for (int jp = 0; jp < 4; jp++) {
                uint32_t bh[4], bl[4];
                const uint32_t off = SWZ((uint32_t)((br + jp * 16) * 128 + bc + ks * 32));
                ldsm_x4(bh, sBh + off);
                ldsm_x4(bl, sBl + off);
#pragma unroll
                for (int mt = 0; mt < 2; mt++) {
                    mma_bf16(acc[mt][2 * jp + 0], ah[mt], bh[0], bh[1]);
                    mma_bf16(acc[mt][2 * jp + 1], ah[mt], bh[2], bh[3]);
                    mma_bf16(acc[mt][2 * jp + 0], ah[mt], bl[0], bl[1]);
                    mma_bf16(acc[mt][2 * jp + 1], ah[mt], bl[2], bl[3]);
                    mma_bf16(acc[mt][2 * jp + 0], al[mt], bh[0], bh[1]);
                    mma_bf16(acc[mt][2 * jp + 1], al[mt], bh[2], bh[3]);
                }
            }
        }
    }
#undef ISSUE2

    const int g = lane >> 2, tg = lane & 3;
#pragma unroll
    for (int mt = 0; mt < 2; mt++) {
        const int row0 = bm + wm * 32 + mt * 16 + g;
#pragma unroll
        for (int nt = 0; nt < 8; nt++) {
            const int col = bn + wn * 64 + nt * 8 + tg * 2;
            const float b0v = bias[col], b1v = bias[col + 1];
            *(float2*)(C + (size_t)row0 * ldc + col) =
                make_float2(acc[mt][nt][0] + b0v, acc[mt][nt][1] + b1v);
            *(float2*)(C + (size_t)(row0 + 8) * ldc + col) =
                make_float2(acc[mt][nt][2] + b0v, acc[mt][nt][3] + b1v);
        }
    }
}

// ---------------------------------------------------------------------------
// Tensor-core flash attention (round-4 proven version).
// ---------------------------------------------------------------------------
#define AT_QOFF 4096u
#define AT_KVOFF 36864u
#define AT_SMEM (4096 + 32768 + 65536)

__global__ __launch_bounds__(256, 1) void attn_tc(
    const __nv_bfloat16* __restrict__ qh_, const __nv_bfloat16* __restrict__ ql_,
    const __nv_bfloat16* __restrict__ kh_, const __nv_bfloat16* __restrict__ kl_,
    const __nv_bfloat16* __restrict__ vh_, const __nv_bfloat16* __restrict__ vl_,
    const float* __restrict__ biases,
    __nv_bfloat16* __restrict__ aohi, __nv_bfloat16* __restrict__ aolo)
{
    extern __shared__ char smem[];
    const uint32_t sb = smem_to_u32(smem);
    const int tid = threadIdx.x, wid = tid >> 5, lane = tid & 31;
    const int g = lane >> 2, tg = lane & 3, qq = lane >> 3, l8 = lane & 7;
    const int qi = blockIdx.x, bh = blockIdx.y;
    const int b = bh >> 4, h = bh & 15;
    const int m0 = wid * 16;
    const size_t hb = (size_t)bh << 16;

    float* bias_s = (float*)smem;
    for (int i = tid; i < 1024; i += 256) bias_s[i] = biases[h * 1024 + i];

    {
        const __nv_bfloat16* srcs[2] = { qh_ + hb + (size_t)(qi * 128) * 64,
                                         ql_ + hb + (size_t)(qi * 128) * 64 };
#pragma unroll
        for (int t = 0; t < 2; t++)
#pragma unroll
            for (int i2 = 0; i2 < 4; i2++) {
                const int idx = tid + 256 * i2;
                const int r = idx >> 3, c = idx & 7;
                cp_async16(sb + AT_QOFF + t * 16384u + SWZ((uint32_t)(r * 128 + c * 16)),
                           srcs[t] + (size_t)r * 64 + c * 8);
            }
        CP_COMMIT();
    }

    const __nv_bfloat16* kvp[4] = { kh_ + hb, kl_ + hb, vh_ + hb, vl_ + hb };

#define ISSUE_KV(kt_, buf_) do {                                                  \
    const uint32_t st = sb + AT_KVOFF + (uint32_t)(buf_) * 32768u;                \
    _Pragma("unroll")                                                             \
    for (int t = 0; t < 4; t++) {                                                 \
        const __nv_bfloat16* gp = kvp[t] + (size_t)((kt_) * 64) * 64;             \
        _Pragma("unroll")                                                         \
        for (int i2 = 0; i2 < 2; i2++) {                                          \
            const int idx = tid + 256 * i2;                                       \
            const int r = idx >> 3, c = idx & 7;                                  \
            cp_async16(st + t * 8192u + SWZ((uint32_t)(r * 128 + c * 16)),        \
                       gp + (size_t)r * 64 + c * 8);                              \
        }                                                                         \
    }                                                                             \
    CP_COMMIT();                                                                  \
} while (0)

    ISSUE_KV(0, 0);
    CP_WAIT_ALL();
    __syncthreads();

    uint32_t qfh[4][4], qfl[4][4];
#pragma unroll
    for (int ks = 0; ks < 4; ks++) {
        const uint32_t off =
            SWZ((uint32_t)((m0 + (qq & 1) * 8 + l8) * 128 + (qq >> 1) * 16 + ks * 32));
        ldsm_x4(qfh[ks], sb + AT_QOFF + off);
        ldsm_x4(qfl[ks], sb + AT_QOFF + 16384u + off);
    }

    float O[8][4];
#pragma unroll
    for (int dt = 0; dt < 8; dt++)
#pragma unroll
        for (int e = 0; e < 4; e++) O[dt][e] = 0.f;
    float mr0 = -1e30f, mr1 = -1e30f, lr0 = 0.f, lr1 = 0.f;

    const int i0 = qi * 128 + m0 + g;
    const int ir0 = i0 >> 5, ic0 = i0 & 31;
    const int ir1 = (i0 + 8) >> 5, ic1 = (i0 + 8) & 31;

    for (int kt = 0; kt < 16; kt++) {
        if (kt > 0) { CP_WAIT_ALL(); __syncthreads(); }
        if (kt < 15) ISSUE_KV(kt + 1, (kt + 1) & 1);
        const uint32_t kb = sb + AT_KVOFF + (uint32_t)(kt & 1) * 32768u;

        float s[8][4];
#pragma unroll
        for (int t = 0; t < 8; t++)
#pragma unroll
            for (int e = 0; e < 4; e++) s[t][e] = 0.f;

#pragma unroll
        for (int ks = 0; ks < 4; ks++) {
#pragma unroll
            for (int jp = 0; jp < 4; jp++) {
                uint32_t khf[4], klf[4];
                const uint32_t off = SWZ((uint32_t)(
                    ((qq >> 1) * 8 + l8 + jp * 16) * 128 + (qq & 1) * 16 + ks * 32));
                ldsm_x4(khf, kb + off);
                ldsm_x4(klf, kb + 8192u + off);
                mma_bf16(s[2 * jp + 0], qfh[ks], khf[0], khf[1]);
                mma_bf16(s[2 * jp + 1], qfh[ks], khf[2], khf[3]);
                mma_bf16(s[2 * jp + 0], qfh[ks], klf[0], klf[1]);
                mma_bf16(s[2 * jp + 1], qfh[ks], klf[2], klf[3]);
                mma_bf16(s[2 * jp + 0], qfl[ks], khf[0], khf[1]);
                mma_bf16(s[2 * jp + 1], qfl[ks], khf[2], khf[3]);
            }
        }

#pragma unroll
        for (int t = 0; t < 8; t++) {
            const int j0 = kt * 64 + t * 8 + tg * 2;
            const int jr0 = j0 >> 5, jc0 = j0 & 31;
            const int jr1 = (j0 + 1) >> 5, jc1 = (j0 + 1) & 31;
            s[t][0] += bias_s[abs(ir0 - jr0) * 32 + abs(ic0 - jc0)];
            s[t][1] += bias_s[abs(ir0 - jr1) * 32 + abs(ic0 - jc1)];
            s[t][2] += bias_s[abs(ir1 - jr0) * 32 + abs(ic1 - jc0)];
            s[t][3] += bias_s[abs(ir1 - jr1) * 32 + abs(ic1 - jc1)];
        }

        float mx0 = -1e30f, mx1 = -1e30f;
#pragma unroll
        for (int t = 0; t < 8; t++) {
            mx0 = fmaxf(mx0, fmaxf(s[t][0], s[t][1]));
            mx1 = fmaxf(mx1, fmaxf(s[t][2], s[t][3]));
        }
        mx0 = fmaxf(mx0, __shfl_xor_sync(0xffffffffu, mx0, 1));
        mx0 = fmaxf(mx0, __shfl_xor_sync(0xffffffffu, mx0, 2));
        mx1 = fmaxf(mx1, __shfl_xor_sync(0xffffffffu, mx1, 1));
        mx1 = fmaxf(mx1, __shfl_xor_sync(0xffffffffu, mx1, 2));
        const float mn0 = fmaxf(mr0, mx0), mn1 = fmaxf(mr1, mx1);
        const float a0 = __expf(mr0 - mn0), a1 = __expf(mr1 - mn1);
        mr0 = mn0; mr1 = mn1;
        float sum0 = 0.f, sum1 = 0.f;
#pragma unroll
        for (int t = 0; t < 8; t++) {
            s[t][0] = __expf(s[t][0] - mn0); sum0 += s[t][0];
            s[t][1] = __expf(s[t][1] - mn0); sum0 += s[t][1];
            s[t][2] = __expf(s[t][2] - mn1); sum1 += s[t][2];
            s[t][3] = __expf(s[t][3] - mn1); sum1 += s[t][3];
        }
        sum0 += __shfl_xor_sync(0xffffffffu, sum0, 1);
        sum0 += __shfl_xor_sync(0xffffffffu, sum0, 2);
        sum1 += __shfl_xor_sync(0xffffffffu, sum1, 1);
        sum1 += __shfl_xor_sync(0xffffffffu, sum1, 2);
        lr0 = lr0 * a0 + sum0;
        lr1 = lr1 * a1 + sum1;
#pragma unroll
        for (int dt = 0; dt < 8; dt++) {
            O[dt][0] *= a0; O[dt][1] *= a0;
            O[dt][2] *= a1; O[dt][3] *= a1;
        }

#pragma unroll
        for (int js = 0; js < 4; js++) {
            uint32_t aph[4], apl[4];
            split2(s[2 * js][0],     s[2 * js][1],     aph[0], apl[0]);
            split2(s[2 * js][2],     s[2 * js][3],     aph[1], apl[1]);
            split2(s[2 * js + 1][0], s[2 * js + 1][1], aph[2], apl[2]);
            split2(s[2 * js + 1][2], s[2 * js + 1][3], aph[3], apl[3]);
#pragma unroll
            for (int dp = 0; dp < 4; dp++) {
                uint32_t vhf[4], vlf[4];
                const uint32_t off = SWZ((uint32_t)(
                    (js * 16 + (qq & 1) * 8 + l8) * 128 + dp * 32 + (qq >> 1) * 16));
                ldsm_x4_t(vhf, kb + 16384u + off);
                ldsm_x4_t(vlf, kb + 24576u + off);
                mma_bf16(O[2 * dp + 0], aph, vhf[0], vhf[1]);
                mma_bf16(O[2 * dp + 1], aph, vhf[2], vhf[3]);
                mma_bf16(O[2 * dp + 0], aph, vlf[0], vlf[1]);
                mma_bf16(O[2 * dp + 1], aph, vlf[2], vlf[3]);
                mma_bf16(O[2 * dp + 0], apl, vhf[0], vhf[1]);
                mma_bf16(O[2 * dp + 1], apl, vhf[2], vhf[3]);
            }
        }
    }
#undef ISSUE_KV

    const float inv0 = 1.f / lr0, inv1 = 1.f / lr1;
    const int t0 = qi * 128 + m0 + g;
    const size_t base0 = ((size_t)(b * 1024 + t0)) * 1024 + h * 64;
    const size_t base1 = base0 + 8 * 1024;
#pragma unroll
    for (int dt = 0; dt < 8; dt++) {
        const int d0 = dt * 8 + tg * 2;
        uint32_t h2, l2;
        split2(O[dt][0] * inv0, O[dt][1] * inv0, h2, l2);
        *(uint32_t*)(aohi + base0 + d0) = h2;
        *(uint32_t*)(aolo + base0 + d0) = l2;
        split2(O[dt][2] * inv1, O[dt][3] * inv1, h2, l2);
        *(uint32_t*)(aohi + base1 + d0) = h2;
        *(uint32_t*)(aolo + base1 + d0) = l2;
    }
}

// ---------------------------------------------------------------------------
extern "C" void kernel_launch(void* const* d_in, const int* in_sizes, int n_in,
                              void* d_out, int out_size)
{
    (void)in_sizes; (void)n_in; (void)out_size;
    const float* x      = (const float*)d_in[0];
    const float* w_qkv  = (const float*)d_in[1];
    const float* biases = (const float*)d_in[2];
    const float* w_out  = (const float*)d_in[4];
    const float* b_out  = (const float*)d_in[5];
    float* out = (float*)d_out;

    __nv_bfloat16 *qh, *ql, *kh, *kl, *vh, *vl;
    __nv_bfloat16 *ahi, *alo, *w1hi, *w1lo, *w2hi, *w2lo, *aohi, *aolo;
    cudaGetSymbolAddress((void**)&qh, g_qh);
    cudaGetSymbolAddress((void**)&ql, g_ql);
    cudaGetSymbolAddress((void**)&kh, g_kh);
    cudaGetSymbolAddress((void**)&kl, g_kl);
    cudaGetSymbolAddress((void**)&vh, g_vh);
    cudaGetSymbolAddress((void**)&vl, g_vl);
    cudaGetSymbolAddress((void**)&ahi, g_ahi);
    cudaGetSymbolAddress((void**)&alo, g_alo);
    cudaGetSymbolAddress((void**)&w1hi, g_w1hi);
    cudaGetSymbolAddress((void**)&w1lo, g_w1lo);
    cudaGetSymbolAddress((void**)&w2hi, g_w2hi);
    cudaGetSymbolAddress((void**)&w2lo, g_w2lo);
    cudaGetSymbolAddress((void**)&aohi, g_aohi);
    cudaGetSymbolAddress((void**)&aolo, g_aolo);

    cudaFuncSetAttribute(gemm1_hmma, cudaFuncAttributeMaxDynamicSharedMemorySize, G1_SMEM);
    cudaFuncSetAttribute(gemm2_hmma, cudaFuncAttributeMaxDynamicSharedMemorySize, GEMM_SMEM);
    cudaFuncSetAttribute(attn_tc, cudaFuncAttributeMaxDynamicSharedMemorySize, AT_SMEM);

    // 1) bf16 hi/lo splits of inputs
    split_bf16<<<8192, 256>>>(x, ahi, alo, 8192 * 1024 / 4);
    split_bf16<<<3072, 256>>>(w_qkv, w1hi, w1lo, 3072 * 1024 / 4);
    split_bf16<<<1024, 256>>>(w_out, w2hi, w2lo, 1024 * 1024 / 4);

    // 2) QKV projection (128x256 tile, 512 threads) -> head-major bf16 hi/lo
    {
        dim3 grid(3072 / 256, 8192 / 128);
        gemm1_hmma<<<grid, 512, G1_SMEM>>>(ahi, alo, w1hi, w1lo,
                                           qh, ql, kh, kl, vh, vl);
    }

    // 3) Tensor-core flash attention -> aohi/aolo
    {
        dim3 grid(8, 128);
        attn_tc<<<grid, 256, AT_SMEM>>>(qh, ql, kh, kl, vh, vl, biases, aohi, aolo);
    }

    // 4) Output projection + bias -> fp32 out
    {
        dim3 grid(1024 / 128, 8192 / 128);
        gemm2_hmma<<<grid, 256, GEMM_SMEM>>>(aohi, aolo, w2hi, w2lo, b_out, out, 1024);
    }
}